// round 8
// baseline (speedup 1.0000x reference)
#include <cuda_runtime.h>

// ---------------------------------------------------------------------------
// SSIM fused kernel: persistent CTAs + cp.async prefetch pipeline, sm_100a.
// (16,3,512,512) fp32 pairs -> mean SSIM.
// Phases 2/3 identical to R7 (TW=128, f32x2-packed, 288 threads).
// ---------------------------------------------------------------------------

#define IMG_H 512
#define IMG_W 512
#define TW 128
#define TH 16
#define IH 26                 // TH + 10
#define PITCH_IU 71           // input smem pitch (float2/ull units)
#define NXP 70                // stored x-pairs per row
#define CS_PITCH 71           // colsum pitch (float2), odd -> conflict-free
#define NTHREADS 288
#define NWARPS 9
#define NB 444                // persistent blocks = 148 SMs x 3 CTAs
#define NTILES (48 * 32 * 4)  // planes x by x bx = 6144

typedef unsigned long long ull;

// ---- compile-time Gaussian weights, double precision (match numpy) --------
constexpr double expser(double x) {
    double t = 1.0, s = 1.0;
    for (int k = 1; k < 100; k++) { t = t * x / (double)k; s += t; }
    return s;
}
constexpr double gk(int i) { double d = (double)(i - 5); return 1.0 / expser(d * d / 4.5); }
constexpr double GSUM = gk(0)+gk(1)+gk(2)+gk(3)+gk(4)+gk(5)+gk(6)+gk(7)+gk(8)+gk(9)+gk(10);
constexpr float WF(int i) { return (float)(gk(i) / GSUM); }
__device__ constexpr float W[11] = {WF(0),WF(1),WF(2),WF(3),WF(4),WF(5),
                                    WF(6),WF(7),WF(8),WF(9),WF(10)};

// ---- f32x2 packed helpers -------------------------------------------------
__device__ __forceinline__ ull fma2(ull a, ull b, ull c) {
    ull d;
    asm("fma.rn.f32x2 %0, %1, %2, %3;" : "=l"(d) : "l"(a), "l"(b), "l"(c));
    return d;
}
__device__ __forceinline__ ull mul2(ull a, ull b) {
    ull d;
    asm("mul.rn.f32x2 %0, %1, %2;" : "=l"(d) : "l"(a), "l"(b));
    return d;
}
__device__ __forceinline__ ull add2(ull a, ull b) {
    ull d;
    asm("add.rn.f32x2 %0, %1, %2;" : "=l"(d) : "l"(a), "l"(b));
    return d;
}
__device__ __forceinline__ ull bc2(float w) {
    ull u;
    asm("mov.b64 %0, {%1, %1};" : "=l"(u) : "f"(w));
    return u;
}
__device__ __forceinline__ ull pk2(float x, float y) {
    ull u;
    asm("mov.b64 %0, {%1, %2};" : "=l"(u) : "f"(x), "f"(y));
    return u;
}
__device__ __forceinline__ float lo2(ull u) {
    float x; asm("{ .reg .f32 hi; mov.b64 {%0, hi}, %1; }" : "=f"(x) : "l"(u));
    return x;
}
__device__ __forceinline__ float hi2(ull u) {
    float y; asm("{ .reg .f32 lo; mov.b64 {lo, %0}, %1; }" : "=f"(y) : "l"(u));
    return y;
}
__device__ __forceinline__ ull neg2(ull a) { return a ^ 0x8000000080000000ULL; }

__device__ double g_sum;
__device__ unsigned g_cnt;

// ---- cp.async prefetch of one tile's halo'd inputs into sI1/sI2 -----------
__device__ __forceinline__ void prefetch_tile(int t, int tid,
                                              const float* __restrict__ img1,
                                              const float* __restrict__ img2,
                                              ull* sI1, ull* sI2) {
    const int bx = t & 3;
    const int by = (t >> 2) & 31;
    const int plane = t >> 7;
    const int ty0 = by * TH;
    const int gx0 = bx * TW - 6;                  // even -> 8B aligned
    const float* p1 = img1 + (size_t)plane * (IMG_H * IMG_W);
    const float* p2 = img2 + (size_t)plane * (IMG_H * IMG_W);

    for (int i = tid; i < IH * NXP; i += NTHREADS) {
        int ly = i / NXP;
        int u  = i - ly * NXP;
        int gy = ty0 - 5 + ly;
        int gx = gx0 + 2 * u;
        bool v = ((unsigned)gy < (unsigned)IMG_H) && ((unsigned)gx < (unsigned)IMG_W);
        int sz = v ? 8 : 0;
        const float* s1 = p1 + gy * IMG_W + gx;
        const float* s2 = p2 + gy * IMG_W + gx;
        unsigned d1 = (unsigned)__cvta_generic_to_shared(sI1 + ly * PITCH_IU + u);
        unsigned d2 = (unsigned)__cvta_generic_to_shared(sI2 + ly * PITCH_IU + u);
        asm volatile("cp.async.ca.shared.global [%0], [%1], 8, %2;"
                     :: "r"(d1), "l"(s1), "r"(sz));
        asm volatile("cp.async.ca.shared.global [%0], [%1], 8, %2;"
                     :: "r"(d2), "l"(s2), "r"(sz));
    }
}

__global__ __launch_bounds__(NTHREADS, 3)
void ssim_main(const float* __restrict__ img1, const float* __restrict__ img2,
               float* __restrict__ out, double inv_n) {
    extern __shared__ ull smu[];
    ull* sI1 = smu;                               // IH * PITCH_IU
    ull* sI2 = smu + IH * PITCH_IU;
    ull* sCS = smu + 2 * IH * PITCH_IU;           // 5 * TH * CS_PITCH
    __shared__ double sRed[NWARPS];

    const int tid = threadIdx.x;
    const int wrp = tid >> 5;
    const int lan = tid & 31;
    const int bid = blockIdx.x;

    double td = 0.0;

    // prologue: prefetch first tile
    prefetch_tile(bid, tid, img1, img2, sI1, sI2);
    asm volatile("cp.async.commit_group;" ::: "memory");

    for (int t = bid; t < NTILES; t += NB) {
        asm volatile("cp.async.wait_group 0;" ::: "memory");
        __syncthreads();                          // sI ready; sCS free

        // ---- phase 2: vertical conv, all 5 quantities per task ------------
        if (tid < NXP * 4) {
            const int u = tid % NXP;
            const int s = tid / NXP;
            const ull* pa = sI1 + (4 * s) * PITCH_IU + u;
            const ull* pb = sI2 + (4 * s) * PITCH_IU + u;
            ull acc[5][4];
#pragma unroll
            for (int q = 0; q < 5; q++)
#pragma unroll
                for (int k = 0; k < 4; k++) acc[q][k] = 0ULL;

#pragma unroll
            for (int j = 0; j < 14; j++) {
                ull a  = pa[j * PITCH_IU];
                ull b  = pb[j * PITCH_IU];
                ull aa = mul2(a, a);
                ull bb = mul2(b, b);
                ull ab = mul2(a, b);
#pragma unroll
                for (int k = 0; k < 4; k++) {
                    if ((unsigned)(j - k) < 11u) {
                        ull wp = bc2(W[j - k]);
                        acc[0][k] = fma2(wp, a,  acc[0][k]);
                        acc[1][k] = fma2(wp, b,  acc[1][k]);
                        acc[2][k] = fma2(wp, aa, acc[2][k]);
                        acc[3][k] = fma2(wp, bb, acc[3][k]);
                        acc[4][k] = fma2(wp, ab, acc[4][k]);
                    }
                }
            }
#pragma unroll
            for (int q = 0; q < 5; q++)
#pragma unroll
                for (int k = 0; k < 4; k++)
                    sCS[(q * TH + 4 * s + k) * CS_PITCH + u] = acc[q][k];
        }
        __syncthreads();                          // sCS ready; sI free

        // ---- prefetch next tile (overlaps phase 3) ------------------------
        {
            int tn = t + NB;
            if (tn < NTILES) prefetch_tile(tn, tid, img1, img2, sI1, sI2);
            asm volatile("cp.async.commit_group;" ::: "memory");
        }

        // ---- phase 3: horizontal conv packed over x-pairs + SSIM ----------
        if (tid < 256) {
            const int y  = tid & 15;
            const int xb = tid >> 4;

            ull Wp[11];
#pragma unroll
            for (int w = 0; w < 11; w++) Wp[w] = bc2(W[w]);

            ull m[5][4];
#pragma unroll
            for (int q = 0; q < 5; q++)
#pragma unroll
                for (int o = 0; o < 4; o++) m[q][o] = 0ULL;

#pragma unroll
            for (int q = 0; q < 5; q++) {
                const ull* cs = sCS + (q * TH + y) * CS_PITCH + 4 * xb;
                ull Pp = cs[0];
#pragma unroll
                for (int i = 1; i < 10; i++) {
                    ull Pi = cs[i];
                    ull S = pk2(hi2(Pp), lo2(Pi));       // S[i-1]
#pragma unroll
                    for (int o = 0; o < 4; o++) {
                        int tt = (i - 1) - o;            // S[o+t], weight W[2t]
                        if (tt >= 0 && tt <= 5)
                            m[q][o] = fma2(Wp[2 * tt], S, m[q][o]);
                        int e = i - o - 1;               // P[o+e+1], weight W[2e+1]
                        if (e >= 0 && e <= 4)
                            m[q][o] = fma2(Wp[2 * e + 1], Pi, m[q][o]);
                    }
                    Pp = Pi;
                }
            }

            const ull C1p  = bc2(1e-4f);
            const ull C2p  = bc2(9e-4f);
            const ull TWOp = bc2(2.0f);
            float local = 0.0f;
#pragma unroll
            for (int o = 0; o < 4; o++) {
                ull m1 = m[0][o], m2 = m[1][o];
                ull m1s = mul2(m1, m1);
                ull m2s = mul2(m2, m2);
                ull m12 = mul2(m1, m2);
                ull nm1 = neg2(m1);
                ull s1  = fma2(nm1, m1, m[2][o]);
                ull s2  = fma2(neg2(m2), m2, m[3][o]);
                ull s12 = fma2(nm1, m2, m[4][o]);
                ull numA = fma2(TWOp, m12, C1p);
                ull numB = fma2(TWOp, s12, C2p);
                ull denA = add2(m1s, add2(m2s, C1p));
                ull denB = add2(s1,  add2(s2,  C2p));
                ull num  = mul2(numA, numB);
                ull den  = mul2(denA, denB);
                local += __fdividef(lo2(num), lo2(den));
                local += __fdividef(hi2(num), hi2(den));
            }
            td += (double)local;
        }
    }

    // -------- final reduction (once per block) -----------------------------
    {
        unsigned mask = 0xffffffffu;
#pragma unroll
        for (int s = 16; s > 0; s >>= 1) td += __shfl_down_sync(mask, td, s);
        if (lan == 0) sRed[wrp] = td;
    }
    __syncthreads();

    if (tid == 0) {
        double s = 0.0;
#pragma unroll
        for (int w = 0; w < NWARPS; w++) s += sRed[w];
        atomicAdd(&g_sum, s);
        __threadfence();
        unsigned done = atomicAdd(&g_cnt, 1);
        if (done == (unsigned)gridDim.x - 1) {
            double v = *((volatile double*)&g_sum);
            out[0] = (float)(v * inv_n);
            g_sum = 0.0;
            g_cnt = 0;
            __threadfence();
        }
    }
}

// ---------------------------------------------------------------------------

extern "C" void kernel_launch(void* const* d_in, const int* in_sizes, int n_in,
                              void* d_out, int out_size) {
    const float* img1 = (const float*)d_in[0];
    const float* img2 = (const float*)d_in[1];
    float* out = (float*)d_out;

    const int total = in_sizes[0];                  // 16*3*512*512

    const int smem_bytes = (2 * IH * PITCH_IU + 5 * TH * CS_PITCH) * (int)sizeof(ull);
    // 2*26*71*8 + 5*16*71*8 = 29536 + 45440 = 74976

    static bool attr_set = false;
    if (!attr_set) {
        cudaFuncSetAttribute(ssim_main, cudaFuncAttributeMaxDynamicSharedMemorySize,
                             smem_bytes);
        attr_set = true;
    }

    ssim_main<<<NB, NTHREADS, smem_bytes>>>(img1, img2, out, 1.0 / (double)total);
}